// round 11
// baseline (speedup 1.0000x reference)
#include <cuda_runtime.h>
#include <math.h>

#define BB 16
#define LL 21504
#define NN 64
#define CC 80
#define GTS 12           // gt param stride
#define TOPK 13
#define NBLK_L 84        // 21504 / 256
#define CAP 1024         // per-(b,n) candidate buffer (max in-box ~650 for 200px box)

// ---------------- scratch (__device__ globals; no allocation) ----------------
__device__ float d_predg[(size_t)BB * LL * 8];          // x,y,a,b,c,det per pred box
__device__ float d_gtg[BB * NN * GTS];                  // cx,cy,cos,sin,hw,hh,a,b,c,det,pad
__device__ int d_gtlab[BB * NN];
__device__ unsigned long long d_padb[BB];               // pad bitmask per batch
__device__ unsigned int d_maxam[BB * NN];               // float bits, atomicMax (nonneg)
__device__ unsigned int d_maxiou[BB * NN];
__device__ unsigned long long d_pos0[(size_t)BB * LL];  // topk membership bitmask
__device__ unsigned long long d_spat[(size_t)BB * LL];  // spatial bitmask (no pad)
__device__ unsigned long long d_pos[(size_t)BB * LL];   // final positive bitmask
__device__ int d_asslab[(size_t)BB * LL];
// candidate buffers
__device__ int d_ccnt[BB * NN];
__device__ unsigned long long d_cand[(size_t)BB * NN * CAP];

// ---------------- bit-exact XLA-shadow ProbIoU ----------------
__device__ __forceinline__ float prob_iou_x(
    float x1, float y1, float a1, float b1, float c1, float det1,
    float x2, float y2, float a2, float b2, float c2, float det2)
{
    float A  = __fadd_rn(a1, a2);
    float Bv = __fadd_rn(b1, b2);
    float Cv = __fadd_rn(c1, c2);
    float denom = __fadd_rn(__fsub_rn(__fmul_rn(A, Bv), __fmul_rn(Cv, Cv)), 1e-7f);
    float dy = __fsub_rn(y1, y2);
    float dx = __fsub_rn(x1, x2);
    float xd = __fsub_rn(x2, x1);
    float t1 = __fdiv_rn(
        __fmul_rn(0.25f, __fadd_rn(__fmul_rn(A, __fmul_rn(dy, dy)),
                                   __fmul_rn(Bv, __fmul_rn(dx, dx)))),
        denom);
    float t2 = __fdiv_rn(
        __fmul_rn(0.5f, __fmul_rn(__fmul_rn(Cv, xd), dy)),
        denom);
    float sq   = __fsqrt_rn(__fmul_rn(det1, det2));
    float den2 = __fadd_rn(__fmul_rn(4.0f, sq), 1e-7f);
    float arg  = __fadd_rn(__fdiv_rn(denom, den2), 1e-7f);
    float t3   = __fmul_rn(0.5f, logf(arg));
    float bd = fminf(fmaxf(__fadd_rn(__fadd_rn(t1, t2), t3), 1e-7f), 100.0f);
    float e  = expf(-bd);
    float s  = __fadd_rn(__fsub_rn(1.0f, e), 1e-7f);
    float hd = __fsqrt_rn(s);
    return fminf(fmaxf(__fsub_rn(1.0f, hd), 0.0f), 1.0f);
}

// align = cls * iou^6 under XLA GPU FTZ semantics (confirmed R4/R6)
__device__ __forceinline__ float align_x(float cls, float iou)
{
    float i2 = __fmul_rn(iou, iou);
    float p6 = __fmul_rn(__fmul_rn(i2, i2), i2);
    if (iou < 0x1p-21f) p6 = 0.0f;
    float al = __fmul_rn(cls, p6);
    if (al < 0x1p-126f) al = 0.0f;
    return al;
}

__device__ __forceinline__ bool spatial_x(float px, float py,
                                          float cx, float cy, float cs, float sn,
                                          float hw, float hh)
{
    float dx = __fsub_rn(px, cx);
    float dy = __fsub_rn(py, cy);
    float sna = -sn;
    float lx = __fsub_rn(__fmul_rn(dx, cs), __fmul_rn(dy, sna));
    float ly = __fadd_rn(__fmul_rn(dx, sna), __fmul_rn(dy, cs));
    return (fabsf(lx) <= hw) && (fabsf(ly) <= hh);
}

__device__ __forceinline__ void gbb_x(float w, float h, float cs, float sn,
                                      float& a, float& b, float& c, float& det)
{
    const float r12 = 1.0f / 12.0f;
    float w2 = __fmul_rn(__fmul_rn(w, w), r12);
    float h2 = __fmul_rn(__fmul_rn(h, h), r12);
    a = __fadd_rn(__fmul_rn(__fmul_rn(w2, cs), cs), __fmul_rn(__fmul_rn(h2, sn), sn));
    b = __fadd_rn(__fmul_rn(__fmul_rn(w2, sn), sn), __fmul_rn(__fmul_rn(h2, cs), cs));
    c = __fmul_rn(__fmul_rn(__fsub_rn(w2, h2), cs), sn);
    det = fmaxf(__fsub_rn(__fmul_rn(a, b), __fmul_rn(c, c)), 0.0f);
}

// ---------------- K_init: single tiny block — GT params + counters + padbits ----
__global__ void k_init(const float* __restrict__ gtb, const int* __restrict__ gtl,
                       const float* __restrict__ pad)
{
    int g = threadIdx.x;              // 1024 threads == BB*NN rows
    {
        const float* p = gtb + (size_t)g * 5;
        float cx = p[0], cy = p[1], w = p[2], h = p[3], ang = p[4];
        float cs = cosf(ang), sn = sinf(ang);
        float a, b, c, det;
        gbb_x(w, h, cs, sn, a, b, c, det);
        float* o = d_gtg + g * GTS;
        o[0] = cx; o[1] = cy; o[2] = cs; o[3] = sn;
        o[4] = __fmul_rn(w, 0.5f); o[5] = __fmul_rn(h, 0.5f);
        o[6] = a; o[7] = b; o[8] = c; o[9] = det;
        o[10] = pad[g]; o[11] = 0.0f;
        d_gtlab[g] = gtl[g];
        d_maxam[g] = 0u;
        d_maxiou[g] = 0u;
        d_ccnt[g] = 0;
    }
    if (g < BB) {
        unsigned long long pb64 = 0ull;
        for (int n = 0; n < NN; n++)
            if (pad[g * NN + n] > 0.0f) pb64 |= (1ull << n);
        d_padb[g] = pb64;
    }
}

// ---------------- K_cand: pred params + spatial mask + candidate push (fused) ----
__global__ void k_cand(const float* __restrict__ anchors, const float* __restrict__ ps,
                       const float* __restrict__ pb)
{
    int blk = blockIdx.x;
    int b = blk / NBLK_L;
    int l = (blk % NBLK_L) * 256 + threadIdx.x;
    int tid = threadIdx.x;
    size_t gid = (size_t)b * LL + l;

    __shared__ float sg[NN * GTS];
    __shared__ int sL[NN];
    for (int i = tid; i < NN * GTS; i += 256) sg[i] = d_gtg[b * NN * GTS + i];
    if (tid < NN) sL[tid] = d_gtlab[b * NN + tid];

    // pred gaussian params (computed here, stored for k_sel/k_assign/k_scores)
    float4 p0, p1;
    {
        const float* p = pb + gid * 5;
        float cx = p[0], cy = p[1], w = p[2], h = p[3], ang = p[4];
        float cs = cosf(ang), sn = sinf(ang);
        float a, bb_, c, det;
        gbb_x(w, h, cs, sn, a, bb_, c, det);
        p0 = make_float4(cx, cy, a, bb_);
        p1 = make_float4(c, det, 0.0f, 0.0f);
        float* o = d_predg + gid * 8;
        ((float4*)o)[0] = p0;
        ((float4*)o)[1] = p1;
    }
    d_pos0[gid] = 0ull;
    __syncthreads();

    float px = anchors[2 * l], py = anchors[2 * l + 1];

    // dense spatial mask over 64 GTs (pure fma, no divergence)
    unsigned long long spat = 0ull;
#pragma unroll 4
    for (int n = 0; n < NN; n++) {
        const float* g = sg + n * GTS;
        if (spatial_x(px, py, g[0], g[1], g[2], g[3], g[4], g[5]))
            spat |= (1ull << n);
    }
    d_spat[gid] = spat;

    // sparse: compute align and push candidates (anchors 0..25 excluded; K_sel covers them)
    if (spat && l >= 26) {
        const float* psr = ps + gid * CC;
        unsigned long long m = spat;
        unsigned long long key_lo = (unsigned long long)(0xFFFFFFFFu - (unsigned)l);
        while (m) {
            int n = __ffsll(m) - 1;
            m &= (m - 1);
            const float* g = sg + n * GTS;
            float iou = prob_iou_x(g[0], g[1], g[6], g[7], g[8], g[9],
                                   p0.x, p0.y, p0.z, p0.w, p1.x, p1.y);
            float cls = __ldg(psr + sL[n]);
            float al = align_x(cls, iou);
            if (al > 0.0f) {
                int row = b * NN + n;
                int slot = atomicAdd(&d_ccnt[row], 1);
                if (slot < CAP)
                    d_cand[(size_t)row * CAP + slot] =
                        ((unsigned long long)__float_as_uint(al) << 32) | key_lo;
            }
        }
    }
}

// ---------------- K_sel: exact top-13 per row from candidate buffer -------------
__device__ __forceinline__ void topk_insert(unsigned long long* loc, unsigned long long key)
{
    if (key > loc[0]) {
        loc[0] = key;
#pragma unroll
        for (int i = 0; i < TOPK - 1; i++) {
            if (loc[i] > loc[i + 1]) {
                unsigned long long t = loc[i]; loc[i] = loc[i + 1]; loc[i + 1] = t;
            } else break;
        }
    }
}

__global__ void k_sel(const float* __restrict__ anchors, const float* __restrict__ ps)
{
    int row = (blockIdx.x * 256 + threadIdx.x) >> 5;   // global warp = row
    int lane = threadIdx.x & 31;
    int b = row >> 6;
    int n = row & 63;

    unsigned long long loc[TOPK];
#pragma unroll
    for (int i = 0; i < TOPK; i++) loc[i] = 0ull;

    int cnt = min(d_ccnt[row], CAP);
    const unsigned long long* buf = d_cand + (size_t)row * CAP;
    for (int i = lane; i < cnt; i += 32)
        topk_insert(loc, buf[i]);

    // anchors 0..25: always candidates (zero-fill exactness), full key incl. zeros
    if (lane < 26) {
        const float* gp = d_gtg + row * GTS;
        float cx = __ldg(gp + 0), cy = __ldg(gp + 1);
        float cs = __ldg(gp + 2), sn = __ldg(gp + 3);
        float hw = __ldg(gp + 4), hh = __ldg(gp + 5);
        int id = lane;
        float px = __ldg(&anchors[2 * id]);
        float py = __ldg(&anchors[2 * id + 1]);
        float ma = 0.0f;
        if (spatial_x(px, py, cx, cy, cs, sn, hw, hh)) {
            float ga = __ldg(gp + 6), gb = __ldg(gp + 7), gc = __ldg(gp + 8), gdet = __ldg(gp + 9);
            const float* pg = d_predg + ((size_t)b * LL + id) * 8;
            float iou = prob_iou_x(cx, cy, ga, gb, gc, gdet,
                                   pg[0], pg[1], pg[2], pg[3], pg[4], pg[5]);
            float cls = __ldg(ps + ((size_t)b * LL + id) * CC + __ldg(&d_gtlab[row]));
            ma = align_x(cls, iou);
        }
        unsigned long long key =
            ((unsigned long long)__float_as_uint(ma) << 32) |
            (unsigned long long)(0xFFFFFFFFu - (unsigned)id);
        topk_insert(loc, key);
    }

    // 13 rounds of warp max-extraction; winner lane scatters its bit
    int consumed = 0;
    unsigned long long nbit = 1ull << n;
    for (int r = 0; r < TOPK; r++) {
        unsigned long long cand = (consumed < TOPK) ? loc[TOPK - 1 - consumed] : 0ull;
        unsigned long long mx = cand;
#pragma unroll
        for (int s = 16; s > 0; s >>= 1) {
            unsigned long long o = __shfl_xor_sync(0xFFFFFFFFu, mx, s);
            if (o > mx) mx = o;
        }
        if (cand == mx && mx != 0ull) {
            consumed++;
            unsigned l = 0xFFFFFFFFu - (unsigned)(mx & 0xFFFFFFFFull);
            atomicOr(&d_pos0[(size_t)b * LL + l], nbit);
        }
    }
}

// ---------------- K2: per-anchor assignment (no smem staging) -------------------
__global__ void k_assign(const float* __restrict__ anchors, const float* __restrict__ ps,
                         const float* __restrict__ gtb, const int* __restrict__ bgp,
                         float* __restrict__ out)
{
    int blk = blockIdx.x;
    int b = blk / NBLK_L;
    int l = (blk % NBLK_L) * 256 + threadIdx.x;
    int lane = threadIdx.x & 31;
    size_t gid = (size_t)b * LL + l;

    const float* gtgb = d_gtg + b * NN * GTS;
    const int* labb = d_gtlab + b * NN;
    const float* psr = ps + gid * CC;

    // positive = topk bits & spatial bits & pad bits (all precomputed)
    unsigned long long pos = d_pos0[gid] & d_spat[gid] & __ldg(&d_padb[b]);

    // lazy pred-param load
    float px2 = 0.f, py2 = 0.f, pa = 0.f, pb_ = 0.f, pc = 0.f, pdet = 0.f;
    if (pos) {
        const float* pg = d_predg + gid * 8;
        float4 p0 = ((const float4*)pg)[0];
        float4 p1 = ((const float4*)pg)[1];
        px2 = p0.x; py2 = p0.y; pa = p0.z; pb_ = p0.w; pc = p1.x; pdet = p1.y;
    }

    // warp-cooperative conflict resolution: pos = (iou == max_n iou) over ALL n
    unsigned cmask = __ballot_sync(0xFFFFFFFFu, __popcll(pos) > 1);
    while (cmask) {
        int src = __ffs(cmask) - 1;
        cmask &= (cmask - 1);
        float bx2 = __shfl_sync(0xFFFFFFFFu, px2, src);
        float by2 = __shfl_sync(0xFFFFFFFFu, py2, src);
        float ba  = __shfl_sync(0xFFFFFFFFu, pa, src);
        float bb  = __shfl_sync(0xFFFFFFFFu, pb_, src);
        float bc  = __shfl_sync(0xFFFFFFFFu, pc, src);
        float bdt = __shfl_sync(0xFFFFFFFFu, pdet, src);
        const float* g0 = gtgb + lane * GTS;
        const float* g1 = gtgb + (lane + 32) * GTS;
        float i0 = prob_iou_x(__ldg(g0 + 0), __ldg(g0 + 1), __ldg(g0 + 6), __ldg(g0 + 7),
                              __ldg(g0 + 8), __ldg(g0 + 9), bx2, by2, ba, bb, bc, bdt);
        float i1 = prob_iou_x(__ldg(g1 + 0), __ldg(g1 + 1), __ldg(g1 + 6), __ldg(g1 + 7),
                              __ldg(g1 + 8), __ldg(g1 + 9), bx2, by2, ba, bb, bc, bdt);
        float mx = fmaxf(i0, i1);
#pragma unroll
        for (int s = 16; s > 0; s >>= 1)
            mx = fmaxf(mx, __shfl_xor_sync(0xFFFFFFFFu, mx, s));
        unsigned long long bits = 0ull;
        if (i0 == mx) bits |= (1ull << lane);
        if (i1 == mx) bits |= (1ull << (lane + 32));
#pragma unroll
        for (int s = 16; s > 0; s >>= 1)
            bits |= __shfl_xor_sync(0xFFFFFFFFu, bits, s);
        if (lane == src) pos = bits;
    }

    // per-GT reductions: max(align*pos), max(iou*pos) via nonneg-float atomicMax
    unsigned long long m = pos;
    while (m) {
        int n = __ffsll(m) - 1;
        m &= (m - 1);
        const float* g = gtgb + n * GTS;
        float iou = prob_iou_x(__ldg(g + 0), __ldg(g + 1), __ldg(g + 6), __ldg(g + 7),
                               __ldg(g + 8), __ldg(g + 9), px2, py2, pa, pb_, pc, pdet);
        float cls = __ldg(psr + __ldg(&labb[n]));
        float al = align_x(cls, iou);
        atomicMax(&d_maxam[b * NN + n], __float_as_uint(al));
        atomicMax(&d_maxiou[b * NN + n], __float_as_uint(iou));
    }

    bool fg = (pos != 0ull);
    int an = fg ? (__ffsll(pos) - 1) : 0;
    int bgv = *bgp;
    int lab = fg ? __ldg(&labb[an]) : bgv;

    out[gid] = (float)lab;                                 // assigned_labels
    const float* gbx = gtb + ((size_t)b * NN + an) * 5;
    float* ob = out + (size_t)BB * LL + gid * 5;           // assigned_bboxes
#pragma unroll
    for (int i = 0; i < 5; i++) ob[i] = fg ? gbx[i] : 0.0f;

    d_pos[gid] = pos;
    d_asslab[gid] = lab;
}

// ---------------- K3: norm + one_hot * norm scores ----------------
__global__ void k_scores(const float* __restrict__ ps, float* __restrict__ out)
{
    int blk = blockIdx.x;
    int b = blk / NBLK_L;
    int l0 = (blk % NBLK_L) * 256;
    int tid = threadIdx.x;
    int l = l0 + tid;
    size_t gid = (size_t)b * LL + l;

    __shared__ float s_norm[256];
    __shared__ int s_lab[256];

    unsigned long long pos = d_pos[gid];
    float norm = 0.0f;
    if (pos) {
        const float* pg = d_predg + gid * 8;
        float4 p0 = ((const float4*)pg)[0];
        float4 p1 = ((const float4*)pg)[1];
        const float* psr = ps + gid * CC;
        unsigned long long m = pos;
        while (m) {
            int n = __ffsll(m) - 1;
            m &= (m - 1);
            int row = b * NN + n;
            const float* g = d_gtg + row * GTS;
            float iou = prob_iou_x(g[0], g[1], g[6], g[7], g[8], g[9],
                                   p0.x, p0.y, p0.z, p0.w, p1.x, p1.y);
            float cls = __ldg(psr + d_gtlab[row]);
            float al = align_x(cls, iou);
            float ma = __uint_as_float(d_maxam[row]);
            float mi = __uint_as_float(d_maxiou[row]);
            float v = __fmul_rn(__fdiv_rn(al, __fadd_rn(ma, 1e-9f)), mi);
            norm = fmaxf(norm, v);
        }
    }
    s_norm[tid] = norm;
    s_lab[tid] = d_asslab[gid];
    __syncthreads();

    // coalesced float4 write of 256 anchors x 80 classes
    float4* sc4 = (float4*)(out + (size_t)BB * LL * 6 + ((size_t)b * LL + l0) * CC);
#pragma unroll
    for (int it = 0; it < 20; it++) {
        int idx = tid + it * 256;           // [0, 5120)
        int a = idx / 20;
        int c4 = (idx - a * 20) * 4;
        float nv = s_norm[a];
        int lb = s_lab[a];
        float4 v;
        v.x = (c4 + 0 == lb) ? nv : 0.0f;
        v.y = (c4 + 1 == lb) ? nv : 0.0f;
        v.z = (c4 + 2 == lb) ? nv : 0.0f;
        v.w = (c4 + 3 == lb) ? nv : 0.0f;
        sc4[idx] = v;
    }
}

// ---------------- launch ----------------
extern "C" void kernel_launch(void* const* d_in, const int* in_sizes, int n_in,
                              void* d_out, int out_size)
{
    const float* pred_scores = (const float*)d_in[0];   // (B,L,C)
    const float* pred_bboxes = (const float*)d_in[1];   // (B,L,5)
    const float* anchors     = (const float*)d_in[2];   // (1,L,2)
    const int*   gt_labels   = (const int*)d_in[3];     // (B,N,1)
    const float* gt_bboxes   = (const float*)d_in[4];   // (B,N,5)
    const float* pad_mask    = (const float*)d_in[5];   // (B,N,1)
    const int*   bg_index    = (const int*)d_in[6];     // scalar
    float* out = (float*)d_out;

    k_init<<<1, BB * NN>>>(gt_bboxes, gt_labels, pad_mask);
    k_cand<<<BB * NBLK_L, 256>>>(anchors, pred_scores, pred_bboxes);
    k_sel<<<(BB * NN) / 8, 256>>>(anchors, pred_scores);
    k_assign<<<BB * NBLK_L, 256>>>(anchors, pred_scores, gt_bboxes, bg_index, out);
    k_scores<<<BB * NBLK_L, 256>>>(pred_scores, out);
}

// round 12
// speedup vs baseline: 1.0754x; 1.0754x over previous
#include <cuda_runtime.h>
#include <math.h>

#define BB 16
#define LL 21504
#define NN 64
#define CC 80
#define GTS 12           // gt param stride
#define TOPK 13
#define NBLK_L 84        // 21504 / 256
#define CAP 1024         // per-(b,n) candidate buffer (max in-box ~650 for 200px box)

// ---------------- scratch (__device__ globals; no allocation) ----------------
__device__ float d_predg[(size_t)BB * LL * 8];          // x,y,a,b,c,det per pred box
__device__ float d_gtg[BB * NN * GTS];                  // cx,cy,cos,sin,hw,hh,a,b,c,det,pad
__device__ int d_gtlab[BB * NN];
__device__ unsigned long long d_padb[BB];               // pad bitmask per batch
__device__ unsigned int d_maxam[BB * NN];               // float bits, atomicMax (nonneg)
__device__ unsigned int d_maxiou[BB * NN];
__device__ unsigned long long d_pos0[(size_t)BB * LL];  // topk membership bitmask
__device__ unsigned long long d_spat[(size_t)BB * LL];  // spatial bitmask (no pad)
__device__ unsigned long long d_pos[(size_t)BB * LL];   // final positive bitmask
__device__ int d_asslab[(size_t)BB * LL];
// candidate buffers
__device__ int d_ccnt[BB * NN];
__device__ unsigned long long d_cand[(size_t)BB * NN * CAP];

// ---------------- bit-exact XLA-shadow ProbIoU ----------------
__device__ __forceinline__ float prob_iou_x(
    float x1, float y1, float a1, float b1, float c1, float det1,
    float x2, float y2, float a2, float b2, float c2, float det2)
{
    float A  = __fadd_rn(a1, a2);
    float Bv = __fadd_rn(b1, b2);
    float Cv = __fadd_rn(c1, c2);
    float denom = __fadd_rn(__fsub_rn(__fmul_rn(A, Bv), __fmul_rn(Cv, Cv)), 1e-7f);
    float dy = __fsub_rn(y1, y2);
    float dx = __fsub_rn(x1, x2);
    float xd = __fsub_rn(x2, x1);
    float t1 = __fdiv_rn(
        __fmul_rn(0.25f, __fadd_rn(__fmul_rn(A, __fmul_rn(dy, dy)),
                                   __fmul_rn(Bv, __fmul_rn(dx, dx)))),
        denom);
    float t2 = __fdiv_rn(
        __fmul_rn(0.5f, __fmul_rn(__fmul_rn(Cv, xd), dy)),
        denom);
    float sq   = __fsqrt_rn(__fmul_rn(det1, det2));
    float den2 = __fadd_rn(__fmul_rn(4.0f, sq), 1e-7f);
    float arg  = __fadd_rn(__fdiv_rn(denom, den2), 1e-7f);
    float t3   = __fmul_rn(0.5f, logf(arg));
    float bd = fminf(fmaxf(__fadd_rn(__fadd_rn(t1, t2), t3), 1e-7f), 100.0f);
    float e  = expf(-bd);
    float s  = __fadd_rn(__fsub_rn(1.0f, e), 1e-7f);
    float hd = __fsqrt_rn(s);
    return fminf(fmaxf(__fsub_rn(1.0f, hd), 0.0f), 1.0f);
}

// align = cls * iou^6 under XLA GPU FTZ semantics (confirmed R4/R6)
__device__ __forceinline__ float align_x(float cls, float iou)
{
    float i2 = __fmul_rn(iou, iou);
    float p6 = __fmul_rn(__fmul_rn(i2, i2), i2);
    if (iou < 0x1p-21f) p6 = 0.0f;
    float al = __fmul_rn(cls, p6);
    if (al < 0x1p-126f) al = 0.0f;
    return al;
}

__device__ __forceinline__ bool spatial_x(float px, float py,
                                          float cx, float cy, float cs, float sn,
                                          float hw, float hh)
{
    float dx = __fsub_rn(px, cx);
    float dy = __fsub_rn(py, cy);
    float sna = -sn;
    float lx = __fsub_rn(__fmul_rn(dx, cs), __fmul_rn(dy, sna));
    float ly = __fadd_rn(__fmul_rn(dx, sna), __fmul_rn(dy, cs));
    return (fabsf(lx) <= hw) && (fabsf(ly) <= hh);
}

__device__ __forceinline__ void gbb_x(float w, float h, float cs, float sn,
                                      float& a, float& b, float& c, float& det)
{
    const float r12 = 1.0f / 12.0f;
    float w2 = __fmul_rn(__fmul_rn(w, w), r12);
    float h2 = __fmul_rn(__fmul_rn(h, h), r12);
    a = __fadd_rn(__fmul_rn(__fmul_rn(w2, cs), cs), __fmul_rn(__fmul_rn(h2, sn), sn));
    b = __fadd_rn(__fmul_rn(__fmul_rn(w2, sn), sn), __fmul_rn(__fmul_rn(h2, cs), cs));
    c = __fmul_rn(__fmul_rn(__fsub_rn(w2, h2), cs), sn);
    det = fmaxf(__fsub_rn(__fmul_rn(a, b), __fmul_rn(c, c)), 0.0f);
}

// ---------------- K_pre: pred params + gt params + zero-init (R10-proven) -------
__global__ void k_pre(const float* __restrict__ pb, const float* __restrict__ gtb,
                      const int* __restrict__ gtl, const float* __restrict__ pad)
{
    int g = blockIdx.x * 256 + threadIdx.x;
    if (g >= BB * LL) return;
    d_pos0[g] = 0ull;
    {
        const float* p = pb + (size_t)g * 5;
        float cx = p[0], cy = p[1], w = p[2], h = p[3], ang = p[4];
        float cs = cosf(ang), sn = sinf(ang);
        float a, b, c, det;
        gbb_x(w, h, cs, sn, a, b, c, det);
        float* o = d_predg + (size_t)g * 8;
        ((float4*)o)[0] = make_float4(cx, cy, a, b);
        ((float4*)o)[1] = make_float4(c, det, 0.0f, 0.0f);
    }
    if (g < BB * NN) {
        const float* p = gtb + (size_t)g * 5;
        float cx = p[0], cy = p[1], w = p[2], h = p[3], ang = p[4];
        float cs = cosf(ang), sn = sinf(ang);
        float a, b, c, det;
        gbb_x(w, h, cs, sn, a, b, c, det);
        float* o = d_gtg + g * GTS;
        o[0] = cx; o[1] = cy; o[2] = cs; o[3] = sn;
        o[4] = __fmul_rn(w, 0.5f); o[5] = __fmul_rn(h, 0.5f);
        o[6] = a; o[7] = b; o[8] = c; o[9] = det;
        o[10] = pad[g]; o[11] = 0.0f;
        d_gtlab[g] = gtl[g];
        d_maxam[g] = 0u;
        d_maxiou[g] = 0u;
        d_ccnt[g] = 0;
    }
    if (g < BB) {
        unsigned long long pb64 = 0ull;
        for (int n = 0; n < NN; n++)
            if (pad[g * NN + n] > 0.0f) pb64 |= (1ull << n);
        d_padb[g] = pb64;
    }
}

// ---------------- K_cand: anchor-major spatial mask + candidate push (R10) ------
__global__ void k_cand(const float* __restrict__ anchors, const float* __restrict__ ps)
{
    int blk = blockIdx.x;
    int b = blk / NBLK_L;
    int l = (blk % NBLK_L) * 256 + threadIdx.x;
    int tid = threadIdx.x;
    size_t gid = (size_t)b * LL + l;

    __shared__ float sg[NN * GTS];
    __shared__ int sL[NN];
    for (int i = tid; i < NN * GTS; i += 256) sg[i] = d_gtg[b * NN * GTS + i];
    if (tid < NN) sL[tid] = d_gtlab[b * NN + tid];
    __syncthreads();

    float px = anchors[2 * l], py = anchors[2 * l + 1];

    // dense spatial mask over 64 GTs (pure fma, no divergence)
    unsigned long long spat = 0ull;
#pragma unroll 4
    for (int n = 0; n < NN; n++) {
        const float* g = sg + n * GTS;
        if (spatial_x(px, py, g[0], g[1], g[2], g[3], g[4], g[5]))
            spat |= (1ull << n);
    }
    d_spat[gid] = spat;

    // sparse: compute align and push candidates (anchors 0..25 excluded; K_sel covers them)
    if (spat && l >= 26) {
        const float* pg = d_predg + gid * 8;
        float4 p0 = ((const float4*)pg)[0];
        float4 p1 = ((const float4*)pg)[1];
        const float* psr = ps + gid * CC;
        unsigned long long m = spat;
        unsigned long long key_lo = (unsigned long long)(0xFFFFFFFFu - (unsigned)l);
        while (m) {
            int n = __ffsll(m) - 1;
            m &= (m - 1);
            const float* g = sg + n * GTS;
            float iou = prob_iou_x(g[0], g[1], g[6], g[7], g[8], g[9],
                                   p0.x, p0.y, p0.z, p0.w, p1.x, p1.y);
            float cls = __ldg(psr + sL[n]);
            float al = align_x(cls, iou);
            if (al > 0.0f) {
                int row = b * NN + n;
                int slot = atomicAdd(&d_ccnt[row], 1);
                if (slot < CAP)
                    d_cand[(size_t)row * CAP + slot] =
                        ((unsigned long long)__float_as_uint(al) << 32) | key_lo;
            }
        }
    }
}

// ---------------- K_sel: exact top-13 per row from candidate buffer -------------
__device__ __forceinline__ void topk_insert(unsigned long long* loc, unsigned long long key)
{
    if (key > loc[0]) {
        loc[0] = key;
#pragma unroll
        for (int i = 0; i < TOPK - 1; i++) {
            if (loc[i] > loc[i + 1]) {
                unsigned long long t = loc[i]; loc[i] = loc[i + 1]; loc[i + 1] = t;
            } else break;
        }
    }
}

__global__ void k_sel(const float* __restrict__ anchors, const float* __restrict__ ps)
{
    int row = (blockIdx.x * 256 + threadIdx.x) >> 5;   // global warp = row
    int lane = threadIdx.x & 31;
    int b = row >> 6;
    int n = row & 63;

    unsigned long long loc[TOPK];
#pragma unroll
    for (int i = 0; i < TOPK; i++) loc[i] = 0ull;

    int cnt = min(d_ccnt[row], CAP);
    const unsigned long long* buf = d_cand + (size_t)row * CAP;
    for (int i = lane; i < cnt; i += 32)
        topk_insert(loc, buf[i]);

    // anchors 0..25: always candidates (zero-fill exactness), full key incl. zeros
    if (lane < 26) {
        const float* gp = d_gtg + row * GTS;
        float cx = __ldg(gp + 0), cy = __ldg(gp + 1);
        float cs = __ldg(gp + 2), sn = __ldg(gp + 3);
        float hw = __ldg(gp + 4), hh = __ldg(gp + 5);
        int id = lane;
        float px = __ldg(&anchors[2 * id]);
        float py = __ldg(&anchors[2 * id + 1]);
        float ma = 0.0f;
        if (spatial_x(px, py, cx, cy, cs, sn, hw, hh)) {
            float ga = __ldg(gp + 6), gb = __ldg(gp + 7), gc = __ldg(gp + 8), gdet = __ldg(gp + 9);
            const float* pg = d_predg + ((size_t)b * LL + id) * 8;
            float iou = prob_iou_x(cx, cy, ga, gb, gc, gdet,
                                   pg[0], pg[1], pg[2], pg[3], pg[4], pg[5]);
            float cls = __ldg(ps + ((size_t)b * LL + id) * CC + __ldg(&d_gtlab[row]));
            ma = align_x(cls, iou);
        }
        unsigned long long key =
            ((unsigned long long)__float_as_uint(ma) << 32) |
            (unsigned long long)(0xFFFFFFFFu - (unsigned)id);
        topk_insert(loc, key);
    }

    // 13 rounds of warp max-extraction; winner lane scatters its bit
    int consumed = 0;
    unsigned long long nbit = 1ull << n;
    for (int r = 0; r < TOPK; r++) {
        unsigned long long cand = (consumed < TOPK) ? loc[TOPK - 1 - consumed] : 0ull;
        unsigned long long mx = cand;
#pragma unroll
        for (int s = 16; s > 0; s >>= 1) {
            unsigned long long o = __shfl_xor_sync(0xFFFFFFFFu, mx, s);
            if (o > mx) mx = o;
        }
        if (cand == mx && mx != 0ull) {
            consumed++;
            unsigned l = 0xFFFFFFFFu - (unsigned)(mx & 0xFFFFFFFFull);
            atomicOr(&d_pos0[(size_t)b * LL + l], nbit);
        }
    }
}

// ---------------- K2: per-anchor assignment (de-smem + block-staged atomics) ----
__global__ void k_assign(const float* __restrict__ anchors, const float* __restrict__ ps,
                         const float* __restrict__ gtb, const int* __restrict__ bgp,
                         float* __restrict__ out)
{
    int blk = blockIdx.x;
    int b = blk / NBLK_L;
    int l = (blk % NBLK_L) * 256 + threadIdx.x;
    int tid = threadIdx.x;
    int lane = tid & 31;
    size_t gid = (size_t)b * LL + l;

    __shared__ unsigned int s_am[NN];
    __shared__ unsigned int s_iou[NN];
    if (tid < NN) { s_am[tid] = 0u; s_iou[tid] = 0u; }
    __syncthreads();

    const float* gtgb = d_gtg + b * NN * GTS;
    const int* labb = d_gtlab + b * NN;
    const float* psr = ps + gid * CC;

    // positive = topk bits & spatial bits & pad bits (all precomputed)
    unsigned long long pos = d_pos0[gid] & d_spat[gid] & __ldg(&d_padb[b]);

    // lazy pred-param load
    float px2 = 0.f, py2 = 0.f, pa = 0.f, pb_ = 0.f, pc = 0.f, pdet = 0.f;
    if (pos) {
        const float* pg = d_predg + gid * 8;
        float4 p0 = ((const float4*)pg)[0];
        float4 p1 = ((const float4*)pg)[1];
        px2 = p0.x; py2 = p0.y; pa = p0.z; pb_ = p0.w; pc = p1.x; pdet = p1.y;
    }

    // warp-cooperative conflict resolution: pos = (iou == max_n iou) over ALL n
    unsigned cmask = __ballot_sync(0xFFFFFFFFu, __popcll(pos) > 1);
    while (cmask) {
        int src = __ffs(cmask) - 1;
        cmask &= (cmask - 1);
        float bx2 = __shfl_sync(0xFFFFFFFFu, px2, src);
        float by2 = __shfl_sync(0xFFFFFFFFu, py2, src);
        float ba  = __shfl_sync(0xFFFFFFFFu, pa, src);
        float bb  = __shfl_sync(0xFFFFFFFFu, pb_, src);
        float bc  = __shfl_sync(0xFFFFFFFFu, pc, src);
        float bdt = __shfl_sync(0xFFFFFFFFu, pdet, src);
        const float* g0 = gtgb + lane * GTS;
        const float* g1 = gtgb + (lane + 32) * GTS;
        float i0 = prob_iou_x(__ldg(g0 + 0), __ldg(g0 + 1), __ldg(g0 + 6), __ldg(g0 + 7),
                              __ldg(g0 + 8), __ldg(g0 + 9), bx2, by2, ba, bb, bc, bdt);
        float i1 = prob_iou_x(__ldg(g1 + 0), __ldg(g1 + 1), __ldg(g1 + 6), __ldg(g1 + 7),
                              __ldg(g1 + 8), __ldg(g1 + 9), bx2, by2, ba, bb, bc, bdt);
        float mx = fmaxf(i0, i1);
#pragma unroll
        for (int s = 16; s > 0; s >>= 1)
            mx = fmaxf(mx, __shfl_xor_sync(0xFFFFFFFFu, mx, s));
        unsigned long long bits = 0ull;
        if (i0 == mx) bits |= (1ull << lane);
        if (i1 == mx) bits |= (1ull << (lane + 32));
#pragma unroll
        for (int s = 16; s > 0; s >>= 1)
            bits |= __shfl_xor_sync(0xFFFFFFFFu, bits, s);
        if (lane == src) pos = bits;
    }

    // per-GT reductions into SMEM (cheap), flushed once per block below
    unsigned long long m = pos;
    while (m) {
        int n = __ffsll(m) - 1;
        m &= (m - 1);
        const float* g = gtgb + n * GTS;
        float iou = prob_iou_x(__ldg(g + 0), __ldg(g + 1), __ldg(g + 6), __ldg(g + 7),
                               __ldg(g + 8), __ldg(g + 9), px2, py2, pa, pb_, pc, pdet);
        float cls = __ldg(psr + __ldg(&labb[n]));
        float al = align_x(cls, iou);
        atomicMax(&s_am[n], __float_as_uint(al));
        atomicMax(&s_iou[n], __float_as_uint(iou));
    }

    bool fg = (pos != 0ull);
    int an = fg ? (__ffsll(pos) - 1) : 0;
    int bgv = *bgp;
    int lab = fg ? __ldg(&labb[an]) : bgv;

    out[gid] = (float)lab;                                 // assigned_labels
    const float* gbx = gtb + ((size_t)b * NN + an) * 5;
    float* ob = out + (size_t)BB * LL + gid * 5;           // assigned_bboxes
#pragma unroll
    for (int i = 0; i < 5; i++) ob[i] = fg ? gbx[i] : 0.0f;

    d_pos[gid] = pos;
    d_asslab[gid] = lab;

    // flush block maxima (<=128 global atomics per block instead of ~2 per positive)
    __syncthreads();
    if (tid < NN) {
        unsigned int v = s_am[tid];
        if (v) atomicMax(&d_maxam[b * NN + tid], v);
    } else if (tid < 2 * NN) {
        unsigned int v = s_iou[tid - NN];
        if (v) atomicMax(&d_maxiou[b * NN + tid - NN], v);
    }
}

// ---------------- K3: norm + one_hot * norm scores ----------------
__global__ void k_scores(const float* __restrict__ ps, float* __restrict__ out)
{
    int blk = blockIdx.x;
    int b = blk / NBLK_L;
    int l0 = (blk % NBLK_L) * 256;
    int tid = threadIdx.x;
    int l = l0 + tid;
    size_t gid = (size_t)b * LL + l;

    __shared__ float s_norm[256];
    __shared__ int s_lab[256];

    unsigned long long pos = d_pos[gid];
    float norm = 0.0f;
    if (pos) {
        const float* pg = d_predg + gid * 8;
        float4 p0 = ((const float4*)pg)[0];
        float4 p1 = ((const float4*)pg)[1];
        const float* psr = ps + gid * CC;
        unsigned long long m = pos;
        while (m) {
            int n = __ffsll(m) - 1;
            m &= (m - 1);
            int row = b * NN + n;
            const float* g = d_gtg + row * GTS;
            float iou = prob_iou_x(g[0], g[1], g[6], g[7], g[8], g[9],
                                   p0.x, p0.y, p0.z, p0.w, p1.x, p1.y);
            float cls = __ldg(psr + d_gtlab[row]);
            float al = align_x(cls, iou);
            float ma = __uint_as_float(d_maxam[row]);
            float mi = __uint_as_float(d_maxiou[row]);
            float v = __fmul_rn(__fdiv_rn(al, __fadd_rn(ma, 1e-9f)), mi);
            norm = fmaxf(norm, v);
        }
    }
    s_norm[tid] = norm;
    s_lab[tid] = d_asslab[gid];
    __syncthreads();

    // coalesced float4 write of 256 anchors x 80 classes
    float4* sc4 = (float4*)(out + (size_t)BB * LL * 6 + ((size_t)b * LL + l0) * CC);
#pragma unroll
    for (int it = 0; it < 20; it++) {
        int idx = tid + it * 256;           // [0, 5120)
        int a = idx / 20;
        int c4 = (idx - a * 20) * 4;
        float nv = s_norm[a];
        int lb = s_lab[a];
        float4 v;
        v.x = (c4 + 0 == lb) ? nv : 0.0f;
        v.y = (c4 + 1 == lb) ? nv : 0.0f;
        v.z = (c4 + 2 == lb) ? nv : 0.0f;
        v.w = (c4 + 3 == lb) ? nv : 0.0f;
        sc4[idx] = v;
    }
}

// ---------------- launch ----------------
extern "C" void kernel_launch(void* const* d_in, const int* in_sizes, int n_in,
                              void* d_out, int out_size)
{
    const float* pred_scores = (const float*)d_in[0];   // (B,L,C)
    const float* pred_bboxes = (const float*)d_in[1];   // (B,L,5)
    const float* anchors     = (const float*)d_in[2];   // (1,L,2)
    const int*   gt_labels   = (const int*)d_in[3];     // (B,N,1)
    const float* gt_bboxes   = (const float*)d_in[4];   // (B,N,5)
    const float* pad_mask    = (const float*)d_in[5];   // (B,N,1)
    const int*   bg_index    = (const int*)d_in[6];     // scalar
    float* out = (float*)d_out;

    k_pre<<<(BB * LL + 255) / 256, 256>>>(pred_bboxes, gt_bboxes, gt_labels, pad_mask);
    k_cand<<<BB * NBLK_L, 256>>>(anchors, pred_scores);
    k_sel<<<(BB * NN) / 8, 256>>>(anchors, pred_scores);
    k_assign<<<BB * NBLK_L, 256>>>(anchors, pred_scores, gt_bboxes, bg_index, out);
    k_scores<<<BB * NBLK_L, 256>>>(pred_scores, out);
}

// round 13
// speedup vs baseline: 1.0795x; 1.0038x over previous
#include <cuda_runtime.h>
#include <math.h>

#define BB 16
#define LL 21504
#define NN 64
#define CC 80
#define GTS 12           // gt param stride
#define TOPK 13
#define NBLK_L 84        // 21504 / 256
#define CAP 1024         // per-(b,n) candidate buffer

// ---------------- scratch (__device__ globals; no allocation) ----------------
__device__ float d_predg[(size_t)BB * LL * 8];          // x,y,a,b,c,det per pred box
__device__ float d_gtg[BB * NN * GTS];                  // cx,cy,cos,sin,hw,hh,a,b,c,det,pad
__device__ int d_gtlab[BB * NN];
__device__ unsigned long long d_padb[BB];               // pad bitmask per batch
__device__ unsigned int d_maxam[BB * NN];               // float bits, atomicMax (nonneg)
__device__ unsigned int d_maxiou[BB * NN];
__device__ unsigned long long d_pos0[(size_t)BB * LL];  // topk&spatial membership bitmask
__device__ unsigned long long d_pos[(size_t)BB * LL];   // final positive bitmask
__device__ int d_asslab[(size_t)BB * LL];
// candidate buffers
__device__ int d_ccnt[BB * NN];
__device__ unsigned long long d_cand[(size_t)BB * NN * CAP];

// ---------------- bit-exact XLA-shadow ProbIoU ----------------
__device__ __forceinline__ float prob_iou_x(
    float x1, float y1, float a1, float b1, float c1, float det1,
    float x2, float y2, float a2, float b2, float c2, float det2)
{
    float A  = __fadd_rn(a1, a2);
    float Bv = __fadd_rn(b1, b2);
    float Cv = __fadd_rn(c1, c2);
    float denom = __fadd_rn(__fsub_rn(__fmul_rn(A, Bv), __fmul_rn(Cv, Cv)), 1e-7f);
    float dy = __fsub_rn(y1, y2);
    float dx = __fsub_rn(x1, x2);
    float xd = __fsub_rn(x2, x1);
    float t1 = __fdiv_rn(
        __fmul_rn(0.25f, __fadd_rn(__fmul_rn(A, __fmul_rn(dy, dy)),
                                   __fmul_rn(Bv, __fmul_rn(dx, dx)))),
        denom);
    float t2 = __fdiv_rn(
        __fmul_rn(0.5f, __fmul_rn(__fmul_rn(Cv, xd), dy)),
        denom);
    float sq   = __fsqrt_rn(__fmul_rn(det1, det2));
    float den2 = __fadd_rn(__fmul_rn(4.0f, sq), 1e-7f);
    float arg  = __fadd_rn(__fdiv_rn(denom, den2), 1e-7f);
    float t3   = __fmul_rn(0.5f, logf(arg));
    float bd = fminf(fmaxf(__fadd_rn(__fadd_rn(t1, t2), t3), 1e-7f), 100.0f);
    float e  = expf(-bd);
    float s  = __fadd_rn(__fsub_rn(1.0f, e), 1e-7f);
    float hd = __fsqrt_rn(s);
    return fminf(fmaxf(__fsub_rn(1.0f, hd), 0.0f), 1.0f);
}

// align = cls * iou^6 under XLA GPU FTZ semantics (confirmed R4/R6)
__device__ __forceinline__ float align_x(float cls, float iou)
{
    float i2 = __fmul_rn(iou, iou);
    float p6 = __fmul_rn(__fmul_rn(i2, i2), i2);
    if (iou < 0x1p-21f) p6 = 0.0f;
    float al = __fmul_rn(cls, p6);
    if (al < 0x1p-126f) al = 0.0f;
    return al;
}

__device__ __forceinline__ bool spatial_x(float px, float py,
                                          float cx, float cy, float cs, float sn,
                                          float hw, float hh)
{
    float dx = __fsub_rn(px, cx);
    float dy = __fsub_rn(py, cy);
    float sna = -sn;
    float lx = __fsub_rn(__fmul_rn(dx, cs), __fmul_rn(dy, sna));
    float ly = __fadd_rn(__fmul_rn(dx, sna), __fmul_rn(dy, cs));
    return (fabsf(lx) <= hw) && (fabsf(ly) <= hh);
}

__device__ __forceinline__ void gbb_x(float w, float h, float cs, float sn,
                                      float& a, float& b, float& c, float& det)
{
    const float r12 = 1.0f / 12.0f;
    float w2 = __fmul_rn(__fmul_rn(w, w), r12);
    float h2 = __fmul_rn(__fmul_rn(h, h), r12);
    a = __fadd_rn(__fmul_rn(__fmul_rn(w2, cs), cs), __fmul_rn(__fmul_rn(h2, sn), sn));
    b = __fadd_rn(__fmul_rn(__fmul_rn(w2, sn), sn), __fmul_rn(__fmul_rn(h2, cs), cs));
    c = __fmul_rn(__fmul_rn(__fsub_rn(w2, h2), cs), sn);
    det = fmaxf(__fsub_rn(__fmul_rn(a, b), __fmul_rn(c, c)), 0.0f);
}

// ---------------- K_pre: pred params + gt params + zero-init -------
__global__ void k_pre(const float* __restrict__ pb, const float* __restrict__ gtb,
                      const int* __restrict__ gtl, const float* __restrict__ pad)
{
    int g = blockIdx.x * 256 + threadIdx.x;
    if (g >= BB * LL) return;
    d_pos0[g] = 0ull;
    {
        const float* p = pb + (size_t)g * 5;
        float cx = p[0], cy = p[1], w = p[2], h = p[3], ang = p[4];
        float cs = cosf(ang), sn = sinf(ang);
        float a, b, c, det;
        gbb_x(w, h, cs, sn, a, b, c, det);
        float* o = d_predg + (size_t)g * 8;
        ((float4*)o)[0] = make_float4(cx, cy, a, b);
        ((float4*)o)[1] = make_float4(c, det, 0.0f, 0.0f);
    }
    if (g < BB * NN) {
        const float* p = gtb + (size_t)g * 5;
        float cx = p[0], cy = p[1], w = p[2], h = p[3], ang = p[4];
        float cs = cosf(ang), sn = sinf(ang);
        float a, b, c, det;
        gbb_x(w, h, cs, sn, a, b, c, det);
        float* o = d_gtg + g * GTS;
        o[0] = cx; o[1] = cy; o[2] = cs; o[3] = sn;
        o[4] = __fmul_rn(w, 0.5f); o[5] = __fmul_rn(h, 0.5f);
        o[6] = a; o[7] = b; o[8] = c; o[9] = det;
        o[10] = pad[g]; o[11] = 0.0f;
        d_gtlab[g] = gtl[g];
        d_maxam[g] = 0u;
        d_maxiou[g] = 0u;
        d_ccnt[g] = 0;
    }
    if (g < BB) {
        unsigned long long pb64 = 0ull;
        for (int n = 0; n < NN; n++)
            if (pad[g * NN + n] > 0.0f) pb64 |= (1ull << n);
        d_padb[g] = pb64;
    }
}

// ---------------- K_cand: vectorized spatial mask + candidate push ------
__global__ void k_cand(const float* __restrict__ anchors, const float* __restrict__ ps)
{
    int blk = blockIdx.x;
    int b = blk / NBLK_L;
    int l = (blk % NBLK_L) * 256 + threadIdx.x;
    int tid = threadIdx.x;
    size_t gid = (size_t)b * LL + l;

    __shared__ float4 sgA[NN];      // cx, cy, cs, sn
    __shared__ float2 sgB[NN];      // hw, hh
    __shared__ float sg[NN * GTS];  // full params (iou path)
    __shared__ int sL[NN];
    for (int i = tid; i < NN * GTS; i += 256) sg[i] = d_gtg[b * NN * GTS + i];
    if (tid < NN) sL[tid] = d_gtlab[b * NN + tid];
    __syncthreads();
    if (tid < NN) {
        const float* g = sg + tid * GTS;
        sgA[tid] = make_float4(g[0], g[1], g[2], g[3]);
        sgB[tid] = make_float2(g[4], g[5]);
    }
    __syncthreads();

    float px = anchors[2 * l], py = anchors[2 * l + 1];

    // dense spatial mask over 64 GTs (2 vector LDS per GT)
    unsigned long long spat = 0ull;
#pragma unroll 8
    for (int n = 0; n < NN; n++) {
        float4 A = sgA[n];
        float2 Bv = sgB[n];
        if (spatial_x(px, py, A.x, A.y, A.z, A.w, Bv.x, Bv.y))
            spat |= (1ull << n);
    }

    // sparse: compute align and push candidates (anchors 0..25 excluded; K_sel covers)
    if (spat && l >= 26) {
        const float* pg = d_predg + gid * 8;
        float4 p0 = ((const float4*)pg)[0];
        float4 p1 = ((const float4*)pg)[1];
        const float* psr = ps + gid * CC;
        unsigned long long m = spat;
        unsigned long long key_lo = (unsigned long long)(0xFFFFFFFFu - (unsigned)l);
        while (m) {
            int n = __ffsll(m) - 1;
            m &= (m - 1);
            const float* g = sg + n * GTS;
            float iou = prob_iou_x(g[0], g[1], g[6], g[7], g[8], g[9],
                                   p0.x, p0.y, p0.z, p0.w, p1.x, p1.y);
            float cls = __ldg(psr + sL[n]);
            float al = align_x(cls, iou);
            if (al > 0.0f) {
                int row = b * NN + n;
                int slot = atomicAdd(&d_ccnt[row], 1);
                if (slot < CAP)
                    d_cand[(size_t)row * CAP + slot] =
                        ((unsigned long long)__float_as_uint(al) << 32) | key_lo;
            }
        }
    }
}

// ---------------- K_sel: exact top-13 per row; spatial folded into scatter ------
__device__ __forceinline__ void topk_insert(unsigned long long* loc, unsigned long long key)
{
    if (key > loc[0]) {
        loc[0] = key;
#pragma unroll
        for (int i = 0; i < TOPK - 1; i++) {
            if (loc[i] > loc[i + 1]) {
                unsigned long long t = loc[i]; loc[i] = loc[i + 1]; loc[i + 1] = t;
            } else break;
        }
    }
}

__global__ void k_sel(const float* __restrict__ anchors, const float* __restrict__ ps)
{
    int row = (blockIdx.x * 256 + threadIdx.x) >> 5;   // global warp = row
    int lane = threadIdx.x & 31;
    int b = row >> 6;
    int n = row & 63;

    unsigned long long loc[TOPK];
#pragma unroll
    for (int i = 0; i < TOPK; i++) loc[i] = 0ull;

    int cnt = min(d_ccnt[row], CAP);
    const unsigned long long* buf = d_cand + (size_t)row * CAP;
    for (int i = lane; i < cnt; i += 32)
        topk_insert(loc, buf[i]);

    // anchors 0..25: always candidates (zero-fill exactness); lane owns id==lane.
    // my_spat tracks spatial(id) so scattering can apply topk & spatial exactly.
    bool my_spat = false;
    if (lane < 26) {
        const float* gp = d_gtg + row * GTS;
        float cx = __ldg(gp + 0), cy = __ldg(gp + 1);
        float cs = __ldg(gp + 2), sn = __ldg(gp + 3);
        float hw = __ldg(gp + 4), hh = __ldg(gp + 5);
        int id = lane;
        float px = __ldg(&anchors[2 * id]);
        float py = __ldg(&anchors[2 * id + 1]);
        float ma = 0.0f;
        my_spat = spatial_x(px, py, cx, cy, cs, sn, hw, hh);
        if (my_spat) {
            float ga = __ldg(gp + 6), gb = __ldg(gp + 7), gc = __ldg(gp + 8), gdet = __ldg(gp + 9);
            const float* pg = d_predg + ((size_t)b * LL + id) * 8;
            float iou = prob_iou_x(cx, cy, ga, gb, gc, gdet,
                                   pg[0], pg[1], pg[2], pg[3], pg[4], pg[5]);
            float cls = __ldg(ps + ((size_t)b * LL + id) * CC + __ldg(&d_gtlab[row]));
            ma = align_x(cls, iou);
        }
        unsigned long long key =
            ((unsigned long long)__float_as_uint(ma) << 32) |
            (unsigned long long)(0xFFFFFFFFu - (unsigned)id);
        topk_insert(loc, key);
    }

    // 13 rounds of warp max-extraction; winner lane scatters (topk & spatial)
    int consumed = 0;
    unsigned long long nbit = 1ull << n;
    for (int r = 0; r < TOPK; r++) {
        unsigned long long cand = (consumed < TOPK) ? loc[TOPK - 1 - consumed] : 0ull;
        unsigned long long mx = cand;
#pragma unroll
        for (int s = 16; s > 0; s >>= 1) {
            unsigned long long o = __shfl_xor_sync(0xFFFFFFFFu, mx, s);
            if (o > mx) mx = o;
        }
        if (cand == mx && mx != 0ull) {
            consumed++;
            // keys with align>0 are spatial by construction (pushed or id<26 under
            // my_spat); zero-valued keys only exist for id==lane<26 -> gate on my_spat
            bool sp_ok = ((mx >> 32) != 0ull) || my_spat;
            if (sp_ok) {
                unsigned l = 0xFFFFFFFFu - (unsigned)(mx & 0xFFFFFFFFull);
                atomicOr(&d_pos0[(size_t)b * LL + l], nbit);
            }
        }
    }
}

// ---------------- K2: per-anchor assignment ----
__global__ void k_assign(const float* __restrict__ anchors, const float* __restrict__ ps,
                         const float* __restrict__ gtb, const int* __restrict__ bgp,
                         float* __restrict__ out)
{
    int blk = blockIdx.x;
    int b = blk / NBLK_L;
    int l = (blk % NBLK_L) * 256 + threadIdx.x;
    int tid = threadIdx.x;
    int lane = tid & 31;
    size_t gid = (size_t)b * LL + l;

    __shared__ unsigned int s_am[NN];
    __shared__ unsigned int s_iou[NN];
    if (tid < NN) { s_am[tid] = 0u; s_iou[tid] = 0u; }
    __syncthreads();

    const float* gtgb = d_gtg + b * NN * GTS;
    const int* labb = d_gtlab + b * NN;
    const float* psr = ps + gid * CC;

    // positive = (topk & spatial) bits & pad bits
    unsigned long long pos = d_pos0[gid] & __ldg(&d_padb[b]);

    // lazy pred-param load
    float px2 = 0.f, py2 = 0.f, pa = 0.f, pb_ = 0.f, pc = 0.f, pdet = 0.f;
    if (pos) {
        const float* pg = d_predg + gid * 8;
        float4 p0 = ((const float4*)pg)[0];
        float4 p1 = ((const float4*)pg)[1];
        px2 = p0.x; py2 = p0.y; pa = p0.z; pb_ = p0.w; pc = p1.x; pdet = p1.y;
    }

    // warp-cooperative conflict resolution: pos = (iou == max_n iou) over ALL n
    unsigned cmask = __ballot_sync(0xFFFFFFFFu, __popcll(pos) > 1);
    while (cmask) {
        int src = __ffs(cmask) - 1;
        cmask &= (cmask - 1);
        float bx2 = __shfl_sync(0xFFFFFFFFu, px2, src);
        float by2 = __shfl_sync(0xFFFFFFFFu, py2, src);
        float ba  = __shfl_sync(0xFFFFFFFFu, pa, src);
        float bb  = __shfl_sync(0xFFFFFFFFu, pb_, src);
        float bc  = __shfl_sync(0xFFFFFFFFu, pc, src);
        float bdt = __shfl_sync(0xFFFFFFFFu, pdet, src);
        const float* g0 = gtgb + lane * GTS;
        const float* g1 = gtgb + (lane + 32) * GTS;
        float i0 = prob_iou_x(__ldg(g0 + 0), __ldg(g0 + 1), __ldg(g0 + 6), __ldg(g0 + 7),
                              __ldg(g0 + 8), __ldg(g0 + 9), bx2, by2, ba, bb, bc, bdt);
        float i1 = prob_iou_x(__ldg(g1 + 0), __ldg(g1 + 1), __ldg(g1 + 6), __ldg(g1 + 7),
                              __ldg(g1 + 8), __ldg(g1 + 9), bx2, by2, ba, bb, bc, bdt);
        float mx = fmaxf(i0, i1);
#pragma unroll
        for (int s = 16; s > 0; s >>= 1)
            mx = fmaxf(mx, __shfl_xor_sync(0xFFFFFFFFu, mx, s));
        unsigned long long bits = 0ull;
        if (i0 == mx) bits |= (1ull << lane);
        if (i1 == mx) bits |= (1ull << (lane + 32));
#pragma unroll
        for (int s = 16; s > 0; s >>= 1)
            bits |= __shfl_xor_sync(0xFFFFFFFFu, bits, s);
        if (lane == src) pos = bits;
    }

    // per-GT reductions into SMEM (cheap), flushed once per block below
    unsigned long long m = pos;
    while (m) {
        int n = __ffsll(m) - 1;
        m &= (m - 1);
        const float* g = gtgb + n * GTS;
        float iou = prob_iou_x(__ldg(g + 0), __ldg(g + 1), __ldg(g + 6), __ldg(g + 7),
                               __ldg(g + 8), __ldg(g + 9), px2, py2, pa, pb_, pc, pdet);
        float cls = __ldg(psr + __ldg(&labb[n]));
        float al = align_x(cls, iou);
        atomicMax(&s_am[n], __float_as_uint(al));
        atomicMax(&s_iou[n], __float_as_uint(iou));
    }

    bool fg = (pos != 0ull);
    int an = fg ? (__ffsll(pos) - 1) : 0;
    int bgv = *bgp;
    int lab = fg ? __ldg(&labb[an]) : bgv;

    out[gid] = (float)lab;                                 // assigned_labels
    const float* gbx = gtb + ((size_t)b * NN + an) * 5;
    float* ob = out + (size_t)BB * LL + gid * 5;           // assigned_bboxes
#pragma unroll
    for (int i = 0; i < 5; i++) ob[i] = fg ? gbx[i] : 0.0f;

    d_pos[gid] = pos;
    d_asslab[gid] = lab;

    // flush block maxima (<=128 global atomics per block)
    __syncthreads();
    if (tid < NN) {
        unsigned int v = s_am[tid];
        if (v) atomicMax(&d_maxam[b * NN + tid], v);
    } else if (tid < 2 * NN) {
        unsigned int v = s_iou[tid - NN];
        if (v) atomicMax(&d_maxiou[b * NN + tid - NN], v);
    }
}

// ---------------- K3: norm + one_hot * norm scores ----------------
__global__ void k_scores(const float* __restrict__ ps, float* __restrict__ out)
{
    int blk = blockIdx.x;
    int b = blk / NBLK_L;
    int l0 = (blk % NBLK_L) * 256;
    int tid = threadIdx.x;
    int l = l0 + tid;
    size_t gid = (size_t)b * LL + l;

    __shared__ float s_norm[256];
    __shared__ int s_lab[256];

    unsigned long long pos = d_pos[gid];
    float norm = 0.0f;
    if (pos) {
        const float* pg = d_predg + gid * 8;
        float4 p0 = ((const float4*)pg)[0];
        float4 p1 = ((const float4*)pg)[1];
        const float* psr = ps + gid * CC;
        unsigned long long m = pos;
        while (m) {
            int n = __ffsll(m) - 1;
            m &= (m - 1);
            int row = b * NN + n;
            const float* g = d_gtg + row * GTS;
            float iou = prob_iou_x(g[0], g[1], g[6], g[7], g[8], g[9],
                                   p0.x, p0.y, p0.z, p0.w, p1.x, p1.y);
            float cls = __ldg(psr + d_gtlab[row]);
            float al = align_x(cls, iou);
            float ma = __uint_as_float(d_maxam[row]);
            float mi = __uint_as_float(d_maxiou[row]);
            float v = __fmul_rn(__fdiv_rn(al, __fadd_rn(ma, 1e-9f)), mi);
            norm = fmaxf(norm, v);
        }
    }
    s_norm[tid] = norm;
    s_lab[tid] = d_asslab[gid];
    __syncthreads();

    // coalesced float4 write of 256 anchors x 80 classes
    float4* sc4 = (float4*)(out + (size_t)BB * LL * 6 + ((size_t)b * LL + l0) * CC);
#pragma unroll
    for (int it = 0; it < 20; it++) {
        int idx = tid + it * 256;           // [0, 5120)
        int a = idx / 20;
        int c4 = (idx - a * 20) * 4;
        float nv = s_norm[a];
        int lb = s_lab[a];
        float4 v;
        v.x = (c4 + 0 == lb) ? nv : 0.0f;
        v.y = (c4 + 1 == lb) ? nv : 0.0f;
        v.z = (c4 + 2 == lb) ? nv : 0.0f;
        v.w = (c4 + 3 == lb) ? nv : 0.0f;
        sc4[idx] = v;
    }
}

// ---------------- launch ----------------
extern "C" void kernel_launch(void* const* d_in, const int* in_sizes, int n_in,
                              void* d_out, int out_size)
{
    const float* pred_scores = (const float*)d_in[0];   // (B,L,C)
    const float* pred_bboxes = (const float*)d_in[1];   // (B,L,5)
    const float* anchors     = (const float*)d_in[2];   // (1,L,2)
    const int*   gt_labels   = (const int*)d_in[3];     // (B,N,1)
    const float* gt_bboxes   = (const float*)d_in[4];   // (B,N,5)
    const float* pad_mask    = (const float*)d_in[5];   // (B,N,1)
    const int*   bg_index    = (const int*)d_in[6];     // scalar
    float* out = (float*)d_out;

    k_pre<<<(BB * LL + 255) / 256, 256>>>(pred_bboxes, gt_bboxes, gt_labels, pad_mask);
    k_cand<<<BB * NBLK_L, 256>>>(anchors, pred_scores);
    k_sel<<<(BB * NN) / 8, 256>>>(anchors, pred_scores);
    k_assign<<<BB * NBLK_L, 256>>>(anchors, pred_scores, gt_bboxes, bg_index, out);
    k_scores<<<BB * NBLK_L, 256>>>(pred_scores, out);
}